// round 10
// baseline (speedup 1.0000x reference)
#include <cuda_runtime.h>
#include <cstdint>

// Fixed shapes for TopKGOATLayer_74156905333517
#define T_TOK   8192
#define DMODEL  4096
#define N_EXP   8
#define RANK    64
#define ER      512
#define KSPLIT  8
#define MAXTIL  64          // worst-case M-tiles per list (8192/128)
#define NLIST   16          // (slot, expert)
#define KS1     4           // K-split factor for gemm1
#define KCHUNK  (DMODEL / KS1)
#define HP_STRIDE ((size_t)NLIST * T_TOK * RANK)

// Scratch (__device__ globals)
__device__ __align__(16) float g_Ar[ER * DMODEL];           // tf32-rounded lora_A
__device__ __align__(16) float g_Br[N_EXP * DMODEL * RANK]; // tf32-rounded lora_B
__device__ __align__(16) float g_Hp[KS1 * NLIST * T_TOK * RANK]; // gemm1 partials
__device__ __align__(16) float g_H[NLIST * T_TOK * RANK];   // compact Hw per (slot,e)
__device__ float g_lp[KSPLIT * T_TOK * N_EXP];
__device__ int   g_cnt[NLIST];
__device__ int   g_list[NLIST * T_TOK];
__device__ float g_wl[NLIST * T_TOK];

// ---------------------------------------------------------------------------
// helpers
// ---------------------------------------------------------------------------
__device__ __forceinline__ unsigned f2tf(float f) {
    unsigned r;
    asm("cvt.rna.tf32.f32 %0, %1;" : "=r"(r) : "f"(f));
    return r;
}

__device__ __forceinline__ void mma_tf32(float c[4], const unsigned a[4], const unsigned b[2]) {
    asm volatile(
        "mma.sync.aligned.m16n8k8.row.col.f32.tf32.tf32.f32 "
        "{%0,%1,%2,%3}, {%4,%5,%6,%7}, {%8,%9}, {%0,%1,%2,%3};\n"
        : "+f"(c[0]), "+f"(c[1]), "+f"(c[2]), "+f"(c[3])
        : "r"(a[0]), "r"(a[1]), "r"(a[2]), "r"(a[3]), "r"(b[0]), "r"(b[1]));
}

__device__ __forceinline__ void cp_async16(uint32_t saddr, const void* gaddr) {
    asm volatile("cp.async.cg.shared.global [%0], [%1], 16;\n" :: "r"(saddr), "l"(gaddr));
}
__device__ __forceinline__ void cp_commit() { asm volatile("cp.async.commit_group;\n"); }
template <int N> __device__ __forceinline__ void cp_wait() {
    asm volatile("cp.async.wait_group %0;\n" :: "n"(N));
}

// ---------------------------------------------------------------------------
// tf32 pre-rounding of LoRA weights + counter reset
// ---------------------------------------------------------------------------
__global__ __launch_bounds__(256) void round_weights(const float4* __restrict__ lA,
                                                     const float4* __restrict__ lB,
                                                     float4* __restrict__ Ar,
                                                     float4* __restrict__ Br,
                                                     int* __restrict__ cnt)
{
    const int n4 = ER * DMODEL / 4;
    int i = blockIdx.x * 256 + threadIdx.x;
    if (i < n4) {
        float4 v = lA[i];
        v.x = __uint_as_float(f2tf(v.x));
        v.y = __uint_as_float(f2tf(v.y));
        v.z = __uint_as_float(f2tf(v.z));
        v.w = __uint_as_float(f2tf(v.w));
        Ar[i] = v;
        float4 u = lB[i];
        u.x = __uint_as_float(f2tf(u.x));
        u.y = __uint_as_float(f2tf(u.y));
        u.z = __uint_as_float(f2tf(u.z));
        u.w = __uint_as_float(f2tf(u.w));
        Br[i] = u;
    }
    if (blockIdx.x == 0 && threadIdx.x < NLIST) cnt[threadIdx.x] = 0;
}

// ---------------------------------------------------------------------------
// Gate partials.  grid = (T/64, KSPLIT=8), 256 thr.
// ---------------------------------------------------------------------------
__global__ __launch_bounds__(256) void gate_part(const float* __restrict__ x,
                                                 const float* __restrict__ gw,
                                                 float* __restrict__ lp)
{
    __shared__ float xs[64][68];
    __shared__ float gs[8][68];

    const int tid  = threadIdx.x;
    const int lane = tid & 31;
    const int warp = tid >> 5;
    const int tok0 = blockIdx.x * 64;
    const int kc0  = blockIdx.y * (DMODEL / KSPLIT);

    float acc[8][8];
#pragma unroll
    for (int i = 0; i < 8; i++)
#pragma unroll
        for (int e = 0; e < 8; e++) acc[i][e] = 0.f;

    const int lr = tid >> 4;
    const int lc = (tid & 15) * 4;

    for (int kc = kc0; kc < kc0 + DMODEL / KSPLIT; kc += 64) {
#pragma unroll
        for (int j = 0; j < 4; j++) {
            float4 v = *(const float4*)&x[(size_t)(tok0 + lr + j * 16) * DMODEL + kc + lc];
            *(float4*)&xs[lr + j * 16][lc] = v;
        }
        if (tid < 128) {
            int rr = tid >> 4;
            float4 v = *(const float4*)&gw[(size_t)rr * DMODEL + kc + lc];
            *(float4*)&gs[rr][lc] = v;
        }
        __syncthreads();

#pragma unroll
        for (int h = 0; h < 2; h++) {
            int kk = lane + h * 32;
            float gv[8];
#pragma unroll
            for (int e = 0; e < 8; e++) gv[e] = gs[e][kk];
#pragma unroll
            for (int i = 0; i < 8; i++) {
                float xv = xs[warp * 8 + i][kk];
#pragma unroll
                for (int e = 0; e < 8; e++) acc[i][e] += xv * gv[e];
            }
        }
        __syncthreads();
    }

#pragma unroll
    for (int off = 16; off > 0; off >>= 1)
#pragma unroll
        for (int i = 0; i < 8; i++)
#pragma unroll
            for (int e = 0; e < 8; e++)
                acc[i][e] += __shfl_xor_sync(0xffffffffu, acc[i][e], off);

#pragma unroll
    for (int i = 0; i < 8; i++) {
        if (lane == i) {
            int tok = tok0 + warp * 8 + i;
            size_t base = ((size_t)blockIdx.y * T_TOK + tok) * N_EXP;
#pragma unroll
            for (int e = 0; e < 8; e++) lp[base + e] = acc[i][e];
        }
    }
}

// ---------------------------------------------------------------------------
// Gate finalize + scatter into per-(slot,expert) lists.
// ---------------------------------------------------------------------------
__global__ __launch_bounds__(256) void gate_fin(const float* __restrict__ lp,
                                                int* __restrict__ cnt,
                                                int* __restrict__ list,
                                                float* __restrict__ wl)
{
    const int tok = blockIdx.x * 256 + threadIdx.x;
    float l[8];
#pragma unroll
    for (int e = 0; e < 8; e++) l[e] = 0.f;
#pragma unroll
    for (int s = 0; s < KSPLIT; s++) {
        size_t base = ((size_t)s * T_TOK + tok) * N_EXP;
#pragma unroll
        for (int e = 0; e < 8; e++) l[e] += lp[base + e];
    }
    float m1 = -1e30f; int e1 = 0;
#pragma unroll
    for (int e = 0; e < 8; e++)
        if (l[e] > m1) { m1 = l[e]; e1 = e; }
    float m2 = -1e30f; int e2 = 0;
#pragma unroll
    for (int e = 0; e < 8; e++)
        if (e != e1 && l[e] > m2) { m2 = l[e]; e2 = e; }
    float w1 = 1.0f / (1.0f + __expf(m2 - m1));

    int p1 = atomicAdd(&cnt[e1], 1);               // slot 0
    list[e1 * T_TOK + p1] = tok;
    wl[e1 * T_TOK + p1] = w1;
    int p2 = atomicAdd(&cnt[8 + e2], 1);           // slot 1
    list[(8 + e2) * T_TOK + p2] = tok;
    wl[(8 + e2) * T_TOK + p2] = 1.0f - w1;
}

// ---------------------------------------------------------------------------
// GEMM1 sparse, K-split x4, 256 thr (8 warps, 4m x 2n, 32x32 warp tile),
// 3-stage cp.async ring with DRAINED TAIL (fixes R9 race).
// A = raw x (HW tf32-truncation), B = RN-rounded A_e. Tile 128x64, BK=32.
// ---------------------------------------------------------------------------
#define G1_AT (128 * 36)
#define G1_BT (64 * 36)
#define G1_ST (G1_AT + G1_BT)
#define G1_DYN (3 * G1_ST * 4)     // 82944 B

__global__ __launch_bounds__(256, 2) void gemm1_sparse(const float* __restrict__ x,
                                                       const float* __restrict__ Ar,
                                                       const int* __restrict__ cnt,
                                                       const int* __restrict__ list,
                                                       float* __restrict__ Hp)
{
    const int bx  = blockIdx.x;
    const int ks  = bx >> 10;                  // NLIST*MAXTIL = 1024 per split
    const int rem = bx & 1023;
    const int le  = rem >> 6;
    const int mt  = rem & (MAXTIL - 1);
    const int n   = cnt[le];
    if (mt * 128 >= n) return;
    const int e = le & 7;

    __shared__ int toks[128];
    extern __shared__ float sm[];

    const int tid  = threadIdx.x;
    const int lane = tid & 31;
    const int warp = tid >> 5;
    const int wm   = warp >> 1;     // 0..3
    const int wn   = warp & 1;      // 0..1

    if (tid < 128) toks[tid] = list[le * T_TOK + mt * 128 + tid];
    __syncthreads();

    const uint32_t smbase = (uint32_t)__cvta_generic_to_shared(sm);
    const int lr = tid >> 3;           // 0..31
    const int lc = (tid & 7) * 4;      // 0..28
    const int kb = ks * KCHUNK;

    const float* ap[4];
#pragma unroll
    for (int j = 0; j < 4; j++)
        ap[j] = &x[(size_t)toks[lr + j * 32] * DMODEL + kb + lc];
    const float* bp[2];
#pragma unroll
    for (int j = 0; j < 2; j++)
        bp[j] = &Ar[((size_t)e * 64 + lr + j * 32) * DMODEL + kb + lc];

    auto issue = [&](int kt) {
        const int s = kt % 3;
        const int k0 = kt * 32;
        const uint32_t sa = smbase + (uint32_t)(s * G1_ST) * 4u;
        const uint32_t sb = sa + G1_AT * 4u;
#pragma unroll
        for (int j = 0; j < 4; j++)
            cp_async16(sa + ((lr + j * 32) * 36 + lc) * 4u, ap[j] + k0);
#pragma unroll
        for (int j = 0; j < 2; j++)
            cp_async16(sb + ((lr + j * 32) * 36 + lc) * 4u, bp[j] + k0);
    };

    float c[2][4][4] = {};
    issue(0); cp_commit();
    issue(1); cp_commit();

    const int r0 = lane >> 2;
    const int cq = lane & 3;
    constexpr int KT = KCHUNK / 32;    // 32

    for (int kt = 0; kt < KT; kt++) {
        // Prefetch kt+2 into buffer (kt+2)%3 == (kt-1)%3; all reads of that
        // buffer finished before the trailing __syncthreads of iter kt-1.
        // Then retire group kt: with {kt, kt+1, kt+2} outstanding, wait<2>
        // guarantees tile kt is complete. Tail (no new issue): wait<0> drains.
        if (kt + 2 < KT) { issue(kt + 2); cp_commit(); cp_wait<2>(); }
        else             { cp_wait<0>(); }
        __syncthreads();

        const float* As = sm + (kt % 3) * G1_ST;
        const float* Bs = As + G1_AT;

#pragma unroll
        for (int kk = 0; kk < 4; kk++) {
            const int k8 = kk * 8;
            unsigned a[2][4], b[4][2];
#pragma unroll
            for (int mi = 0; mi < 2; mi++) {
                int rb = wm * 32 + mi * 16 + r0;
                a[mi][0] = __float_as_uint(As[rb * 36 + k8 + cq]);
                a[mi][1] = __float_as_uint(As[(rb + 8) * 36 + k8 + cq]);
                a[mi][2] = __float_as_uint(As[rb * 36 + k8 + cq + 4]);
                a[mi][3] = __float_as_uint(As[(rb + 8) * 36 + k8 + cq + 4]);
            }
#pragma unroll
            for (int ni = 0; ni < 4; ni++) {
                int nb = wn * 32 + ni * 8 + r0;
                b[ni][0] = __float_as_uint(Bs[nb * 36 + k8 + cq]);
                b[ni][1] = __float_as_uint(Bs[nb * 36 + k8 + cq + 4]);
            }
#pragma unroll
            for (int mi = 0; mi < 2; mi++)
#pragma unroll
                for (int ni = 0; ni < 4; ni++)
                    mma_tf32(c[mi][ni], a[mi], b[ni]);
        }
        __syncthreads();
    }

    const size_t base = (size_t)ks * HP_STRIDE + ((size_t)le * T_TOK + mt * 128) * RANK;
#pragma unroll
    for (int mi = 0; mi < 2; mi++) {
#pragma unroll
        for (int ni = 0; ni < 4; ni++) {
            int row = wm * 32 + mi * 16 + r0;
            int col = wn * 32 + ni * 8 + cq * 2;
            *(float2*)&Hp[base + (size_t)row * RANK + col] =
                make_float2(c[mi][ni][0], c[mi][ni][1]);
            *(float2*)&Hp[base + (size_t)(row + 8) * RANK + col] =
                make_float2(c[mi][ni][2], c[mi][ni][3]);
        }
    }
}

// ---------------------------------------------------------------------------
// reduce_H: H[le][i] = round( w_i * sum_ks Hp[ks][le][i] )
// ---------------------------------------------------------------------------
__global__ __launch_bounds__(256) void reduce_H(const float* __restrict__ Hp,
                                                const int* __restrict__ cnt,
                                                const float* __restrict__ wl,
                                                float* __restrict__ H)
{
    const int le = blockIdx.x >> 6;
    const int mt = blockIdx.x & (MAXTIL - 1);
    const int n  = cnt[le];
    if (mt * 128 >= n) return;

    const int tid  = threadIdx.x;
    const int row  = tid >> 1;
    const int half = (tid & 1) * 32;
    const int i    = mt * 128 + row;
    if (i >= n) return;

    const float w = wl[le * T_TOK + i];
    const size_t rb = ((size_t)le * T_TOK + i) * RANK + half;

#pragma unroll
    for (int q = 0; q < 8; q++) {
        float4 s = *(const float4*)&Hp[rb + q * 4];
#pragma unroll
        for (int ks = 1; ks < KS1; ks++) {
            float4 p = *(const float4*)&Hp[(size_t)ks * HP_STRIDE + rb + q * 4];
            s.x += p.x; s.y += p.y; s.z += p.z; s.w += p.w;
        }
        s.x = __uint_as_float(f2tf(s.x * w));
        s.y = __uint_as_float(f2tf(s.y * w));
        s.z = __uint_as_float(f2tf(s.z * w));
        s.w = __uint_as_float(f2tf(s.w * w));
        *(float4*)&H[rb + q * 4] = s;
    }
}

// ---------------------------------------------------------------------------
// GEMM2 sparse, atomic-free, COALESCED epilogue via SMEM staging.
// Tile 128x128, K=64 one-shot. 256 thr, warps 2x4.
// SLOT 0: out[tok] = v ; SLOT 1: out[tok] += v (unique writer per pass).
// ---------------------------------------------------------------------------
#define G2_HT (128 * 68)
#define G2_DYN (2 * G2_HT * 4)
#define SO_S  132     // staging row stride (floats)

template <int SLOT>
__global__ __launch_bounds__(256, 2) void gemm2_sparse(const float* __restrict__ H,
                                                       const float* __restrict__ Br,
                                                       const int* __restrict__ cnt,
                                                       const int* __restrict__ list,
                                                       float* __restrict__ out)
{
    const int e  = blockIdx.y >> 6;
    const int le = SLOT * 8 + e;
    const int mt = blockIdx.y & (MAXTIL - 1);
    const int n  = cnt[le];
    if (mt * 128 >= n) return;
    const int bn = blockIdx.x * 128;

    __shared__ int toks[128];
    extern __shared__ float sm[];
    float* Hs = sm;
    float* Bs = sm + G2_HT;

    const int tid  = threadIdx.x;
    const int lane = tid & 31;
    const int warp = tid >> 5;
    const int wm   = warp >> 2;
    const int wn   = warp & 3;

    if (tid < 128) toks[tid] = list[le * T_TOK + mt * 128 + tid];

    const uint32_t smbase = (uint32_t)__cvta_generic_to_shared(sm);
    const int lr4 = tid >> 4;          // 0..15
    const int lc4 = (tid & 15) * 4;    // 0..60

#pragma unroll
    for (int j = 0; j < 8; j++) {
        int row = lr4 + j * 16;
        cp_async16(smbase + (uint32_t)(row * 68 + lc4) * 4u,
                   &H[((size_t)le * T_TOK + mt * 128 + row) * RANK + lc4]);
        cp_async16(smbase + (uint32_t)(G2_HT + row * 68 + lc4) * 4u,
                   &Br[((size_t)e * DMODEL + bn + row) * RANK + lc4]);
    }
    cp_commit();
    cp_wait<0>();
    __syncthreads();

    float c[4][4][4] = {};
    const int r0 = lane >> 2;
    const int cq = lane & 3;

#pragma unroll
    for (int kk = 0; kk < 8; kk++) {
        const int k8 = kk * 8;
        unsigned a[4][4], b[4][2];
#pragma unroll
        for (int mi = 0; mi < 4; mi++) {
            int rb = wm * 64 + mi * 16 + r0;
            a[mi][0] = __float_as_uint(Hs[rb * 68 + k8 + cq]);
            a[mi][1] = __float_as_uint(Hs[(rb + 8) * 68 + k8 + cq]);
            a[mi][2] = __float_as_uint(Hs[rb * 68 + k8 + cq + 4]);
            a[mi][3] = __float_as_uint(Hs[(rb + 8) * 68 + k8 + cq + 4]);
        }
#pragma unroll
        for (int ni = 0; ni < 4; ni++) {
            int nb = wn * 32 + ni * 8 + r0;
            b[ni][0] = __float_as_uint(Bs[nb * 68 + k8 + cq]);
            b[ni][1] = __float_as_uint(Bs[nb * 68 + k8 + cq + 4]);
        }
#pragma unroll
        for (int mi = 0; mi < 4; mi++)
#pragma unroll
            for (int ni = 0; ni < 4; ni++)
                mma_tf32(c[mi][ni], a[mi], b[ni]);
    }

    // ---- staged coalesced epilogue: 4 groups of 32 rows ----
    float* so = sm;                     // reuse (mainloop finished)
    const int rr = tid >> 3;            // 0..31
    const int kk8 = (tid & 7) * 4;      // 0..28
#pragma unroll
    for (int g = 0; g < 4; g++) {
        __syncthreads();
        if (wm == (g >> 1)) {
            const int m0 = (g & 1) * 2;
#pragma unroll
            for (int mh = 0; mh < 2; mh++) {
                const int mi = m0 + mh;
                const int rl = mh * 16 + r0;
#pragma unroll
                for (int ni = 0; ni < 4; ni++) {
                    const int col = wn * 32 + ni * 8 + cq * 2;
                    *(float2*)&so[rl * SO_S + col] =
                        make_float2(c[mi][ni][0], c[mi][ni][1]);
                    *(float2*)&so[(rl + 8) * SO_S + col] =
                        make_float2(c[mi][ni][2], c[mi][ni][3]);
                }
            }
        }
        __syncthreads();
        const int gi = mt * 128 + g * 32 + rr;
        if (gi < n) {
            const int t = toks[g * 32 + rr];
            float* op = &out[(size_t)t * DMODEL + bn + kk8];
#pragma unroll
            for (int q = 0; q < 4; q++) {
                float4 v = *(float4*)&so[rr * SO_S + kk8 + q * 32];
                if (SLOT == 1) {
                    float4 o = *(float4*)&op[q * 32];
                    v.x += o.x; v.y += o.y; v.z += o.z; v.w += o.w;
                }
                *(float4*)&op[q * 32] = v;
            }
        }
    }
}

// ---------------------------------------------------------------------------
// launch
// ---------------------------------------------------------------------------
extern "C" void kernel_launch(void* const* d_in, const int* in_sizes, int n_in,
                              void* d_out, int out_size)
{
    const float* x  = (const float*)d_in[0];   // [4,2048,4096]
    const float* gw = (const float*)d_in[1];   // [8,4096]
    const float* lA = (const float*)d_in[2];   // [8,64,4096]
    const float* lB = (const float*)d_in[3];   // [8,4096,64]
    float* out = (float*)d_out;

    float *Hp, *Hc, *lpp, *Ar, *Br, *wlp;
    int *cntp, *listp;
    cudaGetSymbolAddress((void**)&Hp,   g_Hp);
    cudaGetSymbolAddress((void**)&Hc,   g_H);
    cudaGetSymbolAddress((void**)&lpp,  g_lp);
    cudaGetSymbolAddress((void**)&Ar,   g_Ar);
    cudaGetSymbolAddress((void**)&Br,   g_Br);
    cudaGetSymbolAddress((void**)&cntp, g_cnt);
    cudaGetSymbolAddress((void**)&listp,g_list);
    cudaGetSymbolAddress((void**)&wlp,  g_wl);

    cudaFuncSetAttribute((const void*)gemm1_sparse,
                         cudaFuncAttributeMaxDynamicSharedMemorySize, G1_DYN);
    cudaFuncSetAttribute((const void*)gemm2_sparse<0>,
                         cudaFuncAttributeMaxDynamicSharedMemorySize, G2_DYN);
    cudaFuncSetAttribute((const void*)gemm2_sparse<1>,
                         cudaFuncAttributeMaxDynamicSharedMemorySize, G2_DYN);

    // 1) round LoRA weights to tf32 + reset list counters
    round_weights<<<(ER * DMODEL / 4 + 255) / 256, 256>>>(
        (const float4*)lA, (const float4*)lB, (float4*)Ar, (float4*)Br, cntp);
    // 2) gate partials (K-split x8)
    gate_part<<<dim3(T_TOK / 64, KSPLIT), 256>>>(x, gw, lpp);
    // 3) finalize gate + scatter tokens into (slot, expert) lists
    gate_fin<<<T_TOK / 256, 256>>>(lpp, cntp, listp, wlp);
    // 4) sparse GEMM1, K-split x4, 8-warp CTAs, 3-stage pipeline (fixed tail)
    gemm1_sparse<<<KS1 * NLIST * MAXTIL, 256, G1_DYN>>>(x, Ar, cntp, listp, Hp);
    // 5) reduce partials + routing weight + tf32-round -> compact H
    reduce_H<<<NLIST * MAXTIL, 256>>>(Hp, cntp, wlp, Hc);
    // 6) sparse GEMM2 pass A (slot 0): out = v
    gemm2_sparse<0><<<dim3(DMODEL / 128, N_EXP * MAXTIL), 256, G2_DYN>>>(Hc, Br, cntp, listp, out);
    // 7) sparse GEMM2 pass B (slot 1): out += v
    gemm2_sparse<1><<<dim3(DMODEL / 128, N_EXP * MAXTIL), 256, G2_DYN>>>(Hc, Br, cntp, listp, out);
}

// round 11
// speedup vs baseline: 1.0959x; 1.0959x over previous
#include <cuda_runtime.h>
#include <cstdint>

// Fixed shapes for TopKGOATLayer_74156905333517
#define T_TOK   8192
#define DMODEL  4096
#define N_EXP   8
#define RANK    64
#define ER      512
#define KSPLIT  8
#define MAXTIL  64          // worst-case M-tiles per list (8192/128)
#define NLIST   16          // (slot, expert)
#define KS1     4           // K-split factor for gemm1
#define KCHUNK  (DMODEL / KS1)
#define HP_STRIDE ((size_t)NLIST * T_TOK * RANK)

// Scratch (__device__ globals)
__device__ __align__(16) float g_Ar[ER * DMODEL];           // tf32-rounded lora_A
__device__ __align__(16) float g_Br[N_EXP * DMODEL * RANK]; // tf32-rounded lora_B
__device__ __align__(16) float g_Hp[KS1 * NLIST * T_TOK * RANK]; // gemm1 partials
__device__ __align__(16) float g_H[NLIST * T_TOK * RANK];   // compact Hw per (slot,e)
__device__ float g_lp[KSPLIT * T_TOK * N_EXP];
__device__ int   g_cnt[NLIST];
__device__ int   g_list[NLIST * T_TOK];
__device__ float g_wl[NLIST * T_TOK];

// ---------------------------------------------------------------------------
// helpers
// ---------------------------------------------------------------------------
__device__ __forceinline__ unsigned f2tf(float f) {
    unsigned r;
    asm("cvt.rna.tf32.f32 %0, %1;" : "=r"(r) : "f"(f));
    return r;
}

__device__ __forceinline__ void mma_tf32(float c[4], const unsigned a[4], const unsigned b[2]) {
    asm volatile(
        "mma.sync.aligned.m16n8k8.row.col.f32.tf32.tf32.f32 "
        "{%0,%1,%2,%3}, {%4,%5,%6,%7}, {%8,%9}, {%0,%1,%2,%3};\n"
        : "+f"(c[0]), "+f"(c[1]), "+f"(c[2]), "+f"(c[3])
        : "r"(a[0]), "r"(a[1]), "r"(a[2]), "r"(a[3]), "r"(b[0]), "r"(b[1]));
}

__device__ __forceinline__ void cp_async16(uint32_t saddr, const void* gaddr) {
    asm volatile("cp.async.cg.shared.global [%0], [%1], 16;\n" :: "r"(saddr), "l"(gaddr));
}
__device__ __forceinline__ void cp_commit() { asm volatile("cp.async.commit_group;\n"); }
template <int N> __device__ __forceinline__ void cp_wait() {
    asm volatile("cp.async.wait_group %0;\n" :: "n"(N));
}

// ---------------------------------------------------------------------------
// tf32 pre-rounding of LoRA weights + counter reset
// ---------------------------------------------------------------------------
__global__ __launch_bounds__(256) void round_weights(const float4* __restrict__ lA,
                                                     const float4* __restrict__ lB,
                                                     float4* __restrict__ Ar,
                                                     float4* __restrict__ Br,
                                                     int* __restrict__ cnt)
{
    const int n4 = ER * DMODEL / 4;
    int i = blockIdx.x * 256 + threadIdx.x;
    if (i < n4) {
        float4 v = lA[i];
        v.x = __uint_as_float(f2tf(v.x));
        v.y = __uint_as_float(f2tf(v.y));
        v.z = __uint_as_float(f2tf(v.z));
        v.w = __uint_as_float(f2tf(v.w));
        Ar[i] = v;
        float4 u = lB[i];
        u.x = __uint_as_float(f2tf(u.x));
        u.y = __uint_as_float(f2tf(u.y));
        u.z = __uint_as_float(f2tf(u.z));
        u.w = __uint_as_float(f2tf(u.w));
        Br[i] = u;
    }
    if (blockIdx.x == 0 && threadIdx.x < NLIST) cnt[threadIdx.x] = 0;
}

// ---------------------------------------------------------------------------
// Gate partials.  grid = (T/64, KSPLIT=8), 256 thr.
// ---------------------------------------------------------------------------
__global__ __launch_bounds__(256) void gate_part(const float* __restrict__ x,
                                                 const float* __restrict__ gw,
                                                 float* __restrict__ lp)
{
    __shared__ float xs[64][68];
    __shared__ float gs[8][68];

    const int tid  = threadIdx.x;
    const int lane = tid & 31;
    const int warp = tid >> 5;
    const int tok0 = blockIdx.x * 64;
    const int kc0  = blockIdx.y * (DMODEL / KSPLIT);

    float acc[8][8];
#pragma unroll
    for (int i = 0; i < 8; i++)
#pragma unroll
        for (int e = 0; e < 8; e++) acc[i][e] = 0.f;

    const int lr = tid >> 4;
    const int lc = (tid & 15) * 4;

    for (int kc = kc0; kc < kc0 + DMODEL / KSPLIT; kc += 64) {
#pragma unroll
        for (int j = 0; j < 4; j++) {
            float4 v = *(const float4*)&x[(size_t)(tok0 + lr + j * 16) * DMODEL + kc + lc];
            *(float4*)&xs[lr + j * 16][lc] = v;
        }
        if (tid < 128) {
            int rr = tid >> 4;
            float4 v = *(const float4*)&gw[(size_t)rr * DMODEL + kc + lc];
            *(float4*)&gs[rr][lc] = v;
        }
        __syncthreads();

#pragma unroll
        for (int h = 0; h < 2; h++) {
            int kk = lane + h * 32;
            float gv[8];
#pragma unroll
            for (int e = 0; e < 8; e++) gv[e] = gs[e][kk];
#pragma unroll
            for (int i = 0; i < 8; i++) {
                float xv = xs[warp * 8 + i][kk];
#pragma unroll
                for (int e = 0; e < 8; e++) acc[i][e] += xv * gv[e];
            }
        }
        __syncthreads();
    }

#pragma unroll
    for (int off = 16; off > 0; off >>= 1)
#pragma unroll
        for (int i = 0; i < 8; i++)
#pragma unroll
            for (int e = 0; e < 8; e++)
                acc[i][e] += __shfl_xor_sync(0xffffffffu, acc[i][e], off);

#pragma unroll
    for (int i = 0; i < 8; i++) {
        if (lane == i) {
            int tok = tok0 + warp * 8 + i;
            size_t base = ((size_t)blockIdx.y * T_TOK + tok) * N_EXP;
#pragma unroll
            for (int e = 0; e < 8; e++) lp[base + e] = acc[i][e];
        }
    }
}

// ---------------------------------------------------------------------------
// Gate finalize + scatter into per-(slot,expert) lists.
// ---------------------------------------------------------------------------
__global__ __launch_bounds__(256) void gate_fin(const float* __restrict__ lp,
                                                int* __restrict__ cnt,
                                                int* __restrict__ list,
                                                float* __restrict__ wl)
{
    const int tok = blockIdx.x * 256 + threadIdx.x;
    float l[8];
#pragma unroll
    for (int e = 0; e < 8; e++) l[e] = 0.f;
#pragma unroll
    for (int s = 0; s < KSPLIT; s++) {
        size_t base = ((size_t)s * T_TOK + tok) * N_EXP;
#pragma unroll
        for (int e = 0; e < 8; e++) l[e] += lp[base + e];
    }
    float m1 = -1e30f; int e1 = 0;
#pragma unroll
    for (int e = 0; e < 8; e++)
        if (l[e] > m1) { m1 = l[e]; e1 = e; }
    float m2 = -1e30f; int e2 = 0;
#pragma unroll
    for (int e = 0; e < 8; e++)
        if (e != e1 && l[e] > m2) { m2 = l[e]; e2 = e; }
    float w1 = 1.0f / (1.0f + __expf(m2 - m1));

    int p1 = atomicAdd(&cnt[e1], 1);               // slot 0
    list[e1 * T_TOK + p1] = tok;
    wl[e1 * T_TOK + p1] = w1;
    int p2 = atomicAdd(&cnt[8 + e2], 1);           // slot 1
    list[(8 + e2) * T_TOK + p2] = tok;
    wl[(8 + e2) * T_TOK + p2] = 1.0f - w1;
}

// ---------------------------------------------------------------------------
// GEMM1 sparse — REVERTED to the measured-best 73.5us config:
// K-split x4, 128 thr (4 warps 2x2, warp tile 64x32), 2-stage cp.async,
// issue-then-wait<1> with drained tail. A = raw x (HW tf32-truncation).
// ---------------------------------------------------------------------------
#define G1_AT (128 * 36)
#define G1_BT (64 * 36)
#define G1_ST (G1_AT + G1_BT)
#define G1_DYN (2 * G1_ST * 4)

__global__ __launch_bounds__(128, 3) void gemm1_sparse(const float* __restrict__ x,
                                                       const float* __restrict__ Ar,
                                                       const int* __restrict__ cnt,
                                                       const int* __restrict__ list,
                                                       float* __restrict__ Hp)
{
    const int bx  = blockIdx.x;
    const int ks  = bx >> 10;                  // NLIST*MAXTIL = 1024 per split
    const int rem = bx & 1023;
    const int le  = rem >> 6;
    const int mt  = rem & (MAXTIL - 1);
    const int n   = cnt[le];
    if (mt * 128 >= n) return;
    const int e = le & 7;

    __shared__ int toks[128];
    extern __shared__ float sm[];

    const int tid  = threadIdx.x;
    const int lane = tid & 31;
    const int warp = tid >> 5;
    const int wm   = warp >> 1;     // 0..1
    const int wn   = warp & 1;      // 0..1

    toks[tid] = list[le * T_TOK + mt * 128 + tid];
    __syncthreads();

    const uint32_t smbase = (uint32_t)__cvta_generic_to_shared(sm);
    const int lr4 = tid >> 3;          // 0..15
    const int lc4 = (tid & 7) * 4;     // 0..28
    const int kb  = ks * KCHUNK;

    const float* ap[8];
#pragma unroll
    for (int j = 0; j < 8; j++)
        ap[j] = &x[(size_t)toks[lr4 + j * 16] * DMODEL + kb + lc4];
    const float* bp[4];
#pragma unroll
    for (int j = 0; j < 4; j++)
        bp[j] = &Ar[((size_t)e * 64 + lr4 + j * 16) * DMODEL + kb + lc4];

    auto issue = [&](int kt) {
        const int s = kt & 1;
        const int k0 = kt * 32;
        const uint32_t sa = smbase + (uint32_t)(s * G1_ST) * 4u;
        const uint32_t sb = sa + G1_AT * 4u;
#pragma unroll
        for (int j = 0; j < 8; j++)
            cp_async16(sa + ((lr4 + j * 16) * 36 + lc4) * 4u, ap[j] + k0);
#pragma unroll
        for (int j = 0; j < 4; j++)
            cp_async16(sb + ((lr4 + j * 16) * 36 + lc4) * 4u, bp[j] + k0);
    };

    float c[4][4][4] = {};
    issue(0); cp_commit();

    const int r0 = lane >> 2;
    const int cq = lane & 3;
    constexpr int KT = KCHUNK / 32;    // 32

    for (int kt = 0; kt < KT; kt++) {
        if (kt + 1 < KT) { issue(kt + 1); cp_commit(); cp_wait<1>(); }
        else             { cp_wait<0>(); }
        __syncthreads();

        const float* As = sm + (kt & 1) * G1_ST;
        const float* Bs = As + G1_AT;

#pragma unroll
        for (int kk = 0; kk < 4; kk++) {
            const int k8 = kk * 8;
            unsigned a[4][4], b[4][2];
#pragma unroll
            for (int mi = 0; mi < 4; mi++) {
                int rb = wm * 64 + mi * 16 + r0;
                a[mi][0] = __float_as_uint(As[rb * 36 + k8 + cq]);
                a[mi][1] = __float_as_uint(As[(rb + 8) * 36 + k8 + cq]);
                a[mi][2] = __float_as_uint(As[rb * 36 + k8 + cq + 4]);
                a[mi][3] = __float_as_uint(As[(rb + 8) * 36 + k8 + cq + 4]);
            }
#pragma unroll
            for (int ni = 0; ni < 4; ni++) {
                int nb = wn * 32 + ni * 8 + r0;
                b[ni][0] = __float_as_uint(Bs[nb * 36 + k8 + cq]);
                b[ni][1] = __float_as_uint(Bs[nb * 36 + k8 + cq + 4]);
            }
#pragma unroll
            for (int mi = 0; mi < 4; mi++)
#pragma unroll
                for (int ni = 0; ni < 4; ni++)
                    mma_tf32(c[mi][ni], a[mi], b[ni]);
        }
        __syncthreads();
    }

    const size_t base = (size_t)ks * HP_STRIDE + ((size_t)le * T_TOK + mt * 128) * RANK;
#pragma unroll
    for (int mi = 0; mi < 4; mi++) {
#pragma unroll
        for (int ni = 0; ni < 4; ni++) {
            int row = wm * 64 + mi * 16 + r0;
            int col = wn * 32 + ni * 8 + cq * 2;
            *(float2*)&Hp[base + (size_t)row * RANK + col] =
                make_float2(c[mi][ni][0], c[mi][ni][1]);
            *(float2*)&Hp[base + (size_t)(row + 8) * RANK + col] =
                make_float2(c[mi][ni][2], c[mi][ni][3]);
        }
    }
}

// ---------------------------------------------------------------------------
// reduce_H: H[le][i] = round( w_i * sum_ks Hp[ks][le][i] )
// ---------------------------------------------------------------------------
__global__ __launch_bounds__(256) void reduce_H(const float* __restrict__ Hp,
                                                const int* __restrict__ cnt,
                                                const float* __restrict__ wl,
                                                float* __restrict__ H)
{
    const int le = blockIdx.x >> 6;
    const int mt = blockIdx.x & (MAXTIL - 1);
    const int n  = cnt[le];
    if (mt * 128 >= n) return;

    const int tid  = threadIdx.x;
    const int row  = tid >> 1;
    const int half = (tid & 1) * 32;
    const int i    = mt * 128 + row;
    if (i >= n) return;

    const float w = wl[le * T_TOK + i];
    const size_t rb = ((size_t)le * T_TOK + i) * RANK + half;

#pragma unroll
    for (int q = 0; q < 8; q++) {
        float4 s = *(const float4*)&Hp[rb + q * 4];
#pragma unroll
        for (int ks = 1; ks < KS1; ks++) {
            float4 p = *(const float4*)&Hp[(size_t)ks * HP_STRIDE + rb + q * 4];
            s.x += p.x; s.y += p.y; s.z += p.z; s.w += p.w;
        }
        s.x = __uint_as_float(f2tf(s.x * w));
        s.y = __uint_as_float(f2tf(s.y * w));
        s.z = __uint_as_float(f2tf(s.z * w));
        s.w = __uint_as_float(f2tf(s.w * w));
        *(float4*)&H[rb + q * 4] = s;
    }
}

// ---------------------------------------------------------------------------
// GEMM2 sparse: 2 N-tiles per CTA, H loaded ONCE, B double-buffered.
// Tile 128x128 per bn iter, K=64 one-shot. 256 thr, warps 2x4.
// Staging for the coalesced epilogue reuses the B0 buffer (free after its
// compute; B1 lives in its own buffer).
// SLOT 0: out[tok] = v ; SLOT 1: out[tok] += v.
// ---------------------------------------------------------------------------
#define G2_HT (128 * 68)                 // floats per tile buffer
#define G2_DYN (3 * G2_HT * 4)           // H + B0 + B1 = 104448 B
#define SO_S  132                        // staging row stride (floats)

template <int SLOT>
__global__ __launch_bounds__(256, 2) void gemm2_sparse(const float* __restrict__ H,
                                                       const float* __restrict__ Br,
                                                       const int* __restrict__ cnt,
                                                       const int* __restrict__ list,
                                                       float* __restrict__ out)
{
    const int e  = blockIdx.y >> 6;
    const int le = SLOT * 8 + e;
    const int mt = blockIdx.y & (MAXTIL - 1);
    const int n  = cnt[le];
    if (mt * 128 >= n) return;
    const int bn0 = blockIdx.x * 256;

    __shared__ int toks[128];
    extern __shared__ float sm[];
    float* Hs = sm;                       // H tile (persistent)
    float* Bb[2] = { sm + G2_HT, sm + 2 * G2_HT };
    float* so = sm + G2_HT;               // staging == B0 region

    const int tid  = threadIdx.x;
    const int lane = tid & 31;
    const int warp = tid >> 5;
    const int wm   = warp >> 2;
    const int wn   = warp & 3;

    if (tid < 128) toks[tid] = list[le * T_TOK + mt * 128 + tid];

    const uint32_t smbase = (uint32_t)__cvta_generic_to_shared(sm);
    const int lr4 = tid >> 4;          // 0..15
    const int lc4 = (tid & 15) * 4;    // 0..60

    // group0 = {H, B(bn0)}, group1 = {B(bn0+128)}
#pragma unroll
    for (int j = 0; j < 8; j++) {
        int row = lr4 + j * 16;
        cp_async16(smbase + (uint32_t)(row * 68 + lc4) * 4u,
                   &H[((size_t)le * T_TOK + mt * 128 + row) * RANK + lc4]);
        cp_async16(smbase + (uint32_t)(G2_HT + row * 68 + lc4) * 4u,
                   &Br[((size_t)e * DMODEL + bn0 + row) * RANK + lc4]);
    }
    cp_commit();
#pragma unroll
    for (int j = 0; j < 8; j++) {
        int row = lr4 + j * 16;
        cp_async16(smbase + (uint32_t)(2 * G2_HT + row * 68 + lc4) * 4u,
                   &Br[((size_t)e * DMODEL + bn0 + 128 + row) * RANK + lc4]);
    }
    cp_commit();

    const int r0 = lane >> 2;
    const int cq = lane & 3;
    const int rr = tid >> 3;            // 0..31 (epilogue row)
    const int kk8 = (tid & 7) * 4;      // 0..28

#pragma unroll 1
    for (int t = 0; t < 2; t++) {
        if (t == 0) cp_wait<1>();       // H + B0 complete
        else        cp_wait<0>();       // B1 complete
        __syncthreads();

        const float* Bs = Bb[t];
        const int bn = bn0 + t * 128;

        float c[4][4][4] = {};
#pragma unroll
        for (int kk = 0; kk < 8; kk++) {
            const int k8 = kk * 8;
            unsigned a[4][4], b[4][2];
#pragma unroll
            for (int mi = 0; mi < 4; mi++) {
                int rb = wm * 64 + mi * 16 + r0;
                a[mi][0] = __float_as_uint(Hs[rb * 68 + k8 + cq]);
                a[mi][1] = __float_as_uint(Hs[(rb + 8) * 68 + k8 + cq]);
                a[mi][2] = __float_as_uint(Hs[rb * 68 + k8 + cq + 4]);
                a[mi][3] = __float_as_uint(Hs[(rb + 8) * 68 + k8 + cq + 4]);
            }
#pragma unroll
            for (int ni = 0; ni < 4; ni++) {
                int nb = wn * 32 + ni * 8 + r0;
                b[ni][0] = __float_as_uint(Bs[nb * 68 + k8 + cq]);
                b[ni][1] = __float_as_uint(Bs[nb * 68 + k8 + cq + 4]);
            }
#pragma unroll
            for (int mi = 0; mi < 4; mi++)
#pragma unroll
                for (int ni = 0; ni < 4; ni++)
                    mma_tf32(c[mi][ni], a[mi], b[ni]);
        }

        // ---- staged coalesced epilogue: 4 groups of 32 rows ----
        // Staging area = B0 region: free in t=0 (its compute just finished,
        // B1 is in the other buffer) and free in t=1.
#pragma unroll
        for (int g = 0; g < 4; g++) {
            __syncthreads();
            if (wm == (g >> 1)) {
                const int m0 = (g & 1) * 2;
#pragma unroll
                for (int mh = 0; mh < 2; mh++) {
                    const int mi = m0 + mh;
                    const int rl = mh * 16 + r0;
#pragma unroll
                    for (int ni = 0; ni < 4; ni++) {
                        const int col = wn * 32 + ni * 8 + cq * 2;
                        *(float2*)&so[rl * SO_S + col] =
                            make_float2(c[mi][ni][0], c[mi][ni][1]);
                        *(float2*)&so[(rl + 8) * SO_S + col] =
                            make_float2(c[mi][ni][2], c[mi][ni][3]);
                    }
                }
            }
            __syncthreads();
            const int gi = mt * 128 + g * 32 + rr;
            if (gi < n) {
                const int tk = toks[g * 32 + rr];
                float* op = &out[(size_t)tk * DMODEL + bn + kk8];
#pragma unroll
                for (int q = 0; q < 4; q++) {
                    float4 v = *(float4*)&so[rr * SO_S + kk8 + q * 32];
                    if (SLOT == 1) {
                        float4 o = *(float4*)&op[q * 32];
                        v.x += o.x; v.y += o.y; v.z += o.z; v.w += o.w;
                    }
                    *(float4*)&op[q * 32] = v;
                }
            }
        }
        __syncthreads();   // staging drained before t=1 reuses it / exits
    }
}

// ---------------------------------------------------------------------------
// launch
// ---------------------------------------------------------------------------
extern "C" void kernel_launch(void* const* d_in, const int* in_sizes, int n_in,
                              void* d_out, int out_size)
{
    const float* x  = (const float*)d_in[0];   // [4,2048,4096]
    const float* gw = (const float*)d_in[1];   // [8,4096]
    const float* lA = (const float*)d_in[2];   // [8,64,4096]
    const float* lB = (const float*)d_in[3];   // [8,4096,64]
    float* out = (float*)d_out;

    float *Hp, *Hc, *lpp, *Ar, *Br, *wlp;
    int *cntp, *listp;
    cudaGetSymbolAddress((void**)&Hp,   g_Hp);
    cudaGetSymbolAddress((void**)&Hc,   g_H);
    cudaGetSymbolAddress((void**)&lpp,  g_lp);
    cudaGetSymbolAddress((void**)&Ar,   g_Ar);
    cudaGetSymbolAddress((void**)&Br,   g_Br);
    cudaGetSymbolAddress((void**)&cntp, g_cnt);
    cudaGetSymbolAddress((void**)&listp,g_list);
    cudaGetSymbolAddress((void**)&wlp,  g_wl);

    cudaFuncSetAttribute((const void*)gemm1_sparse,
                         cudaFuncAttributeMaxDynamicSharedMemorySize, G1_DYN);
    cudaFuncSetAttribute((const void*)gemm2_sparse<0>,
                         cudaFuncAttributeMaxDynamicSharedMemorySize, G2_DYN);
    cudaFuncSetAttribute((const void*)gemm2_sparse<1>,
                         cudaFuncAttributeMaxDynamicSharedMemorySize, G2_DYN);

    // 1) round LoRA weights to tf32 + reset list counters
    round_weights<<<(ER * DMODEL / 4 + 255) / 256, 256>>>(
        (const float4*)lA, (const float4*)lB, (float4*)Ar, (float4*)Br, cntp);
    // 2) gate partials (K-split x8)
    gate_part<<<dim3(T_TOK / 64, KSPLIT), 256>>>(x, gw, lpp);
    // 3) finalize gate + scatter tokens into (slot, expert) lists
    gate_fin<<<T_TOK / 256, 256>>>(lpp, cntp, listp, wlp);
    // 4) sparse GEMM1 (reverted to measured-best config)
    gemm1_sparse<<<KS1 * NLIST * MAXTIL, 128, G1_DYN>>>(x, Ar, cntp, listp, Hp);
    // 5) reduce partials + routing weight + tf32-round -> compact H
    reduce_H<<<NLIST * MAXTIL, 256>>>(Hp, cntp, wlp, Hc);
    // 6) sparse GEMM2 pass A (slot 0): out = v   (2 N-tiles per CTA)
    gemm2_sparse<0><<<dim3(DMODEL / 256, N_EXP * MAXTIL), 256, G2_DYN>>>(Hc, Br, cntp, listp, out);
    // 7) sparse GEMM2 pass B (slot 1): out += v
    gemm2_sparse<1><<<dim3(DMODEL / 256, N_EXP * MAXTIL), 256, G2_DYN>>>(Hc, Br, cntp, listp, out);
}

// round 12
// speedup vs baseline: 1.1118x; 1.0145x over previous
#include <cuda_runtime.h>
#include <cstdint>

// Fixed shapes for TopKGOATLayer_74156905333517
#define T_TOK   8192
#define DMODEL  4096
#define N_EXP   8
#define RANK    64
#define ER      512
#define KSPLIT  8
#define KCH_G   (DMODEL / KSPLIT)   // 512, gate k-chunk
#define MAXTIL  64          // worst-case M-tiles per list (8192/128)
#define NLIST   16          // (slot, expert)
#define KS1     4           // K-split factor for gemm1
#define KCHUNK  (DMODEL / KS1)
#define HP_STRIDE ((size_t)NLIST * T_TOK * RANK)

// Scratch (__device__ globals)
__device__ __align__(16) float g_Ar[ER * DMODEL];           // tf32-rounded lora_A
__device__ __align__(16) float g_Br[N_EXP * DMODEL * RANK]; // tf32-rounded lora_B
__device__ __align__(16) float g_Hp[KS1 * NLIST * T_TOK * RANK]; // gemm1 partials
__device__ __align__(16) float g_H[NLIST * T_TOK * RANK];   // compact Hw per (slot,e)
__device__ float g_lp[KSPLIT * T_TOK * N_EXP];
__device__ int   g_cnt[NLIST];
__device__ int   g_list[NLIST * T_TOK];
__device__ float g_wl[NLIST * T_TOK];

// ---------------------------------------------------------------------------
// helpers
// ---------------------------------------------------------------------------
__device__ __forceinline__ unsigned f2tf(float f) {
    unsigned r;
    asm("cvt.rna.tf32.f32 %0, %1;" : "=r"(r) : "f"(f));
    return r;
}

__device__ __forceinline__ void mma_tf32(float c[4], const unsigned a[4], const unsigned b[2]) {
    asm volatile(
        "mma.sync.aligned.m16n8k8.row.col.f32.tf32.tf32.f32 "
        "{%0,%1,%2,%3}, {%4,%5,%6,%7}, {%8,%9}, {%0,%1,%2,%3};\n"
        : "+f"(c[0]), "+f"(c[1]), "+f"(c[2]), "+f"(c[3])
        : "r"(a[0]), "r"(a[1]), "r"(a[2]), "r"(a[3]), "r"(b[0]), "r"(b[1]));
}

__device__ __forceinline__ void cp_async16(uint32_t saddr, const void* gaddr) {
    asm volatile("cp.async.cg.shared.global [%0], [%1], 16;\n" :: "r"(saddr), "l"(gaddr));
}
__device__ __forceinline__ void cp_commit() { asm volatile("cp.async.commit_group;\n"); }
template <int N> __device__ __forceinline__ void cp_wait() {
    asm volatile("cp.async.wait_group %0;\n" :: "n"(N));
}

// ---------------------------------------------------------------------------
// tf32 pre-rounding of LoRA weights + counter reset
// ---------------------------------------------------------------------------
__global__ __launch_bounds__(256) void round_weights(const float4* __restrict__ lA,
                                                     const float4* __restrict__ lB,
                                                     float4* __restrict__ Ar,
                                                     float4* __restrict__ Br,
                                                     int* __restrict__ cnt)
{
    const int n4 = ER * DMODEL / 4;
    int i = blockIdx.x * 256 + threadIdx.x;
    if (i < n4) {
        float4 v = lA[i];
        v.x = __uint_as_float(f2tf(v.x));
        v.y = __uint_as_float(f2tf(v.y));
        v.z = __uint_as_float(f2tf(v.z));
        v.w = __uint_as_float(f2tf(v.w));
        Ar[i] = v;
        float4 u = lB[i];
        u.x = __uint_as_float(f2tf(u.x));
        u.y = __uint_as_float(f2tf(u.y));
        u.z = __uint_as_float(f2tf(u.z));
        u.w = __uint_as_float(f2tf(u.w));
        Br[i] = u;
    }
    if (blockIdx.x == 0 && threadIdx.x < NLIST) cnt[threadIdx.x] = 0;
}

// ---------------------------------------------------------------------------
// Gate partials — streaming rewrite. grid = (T/64, KSPLIT=8), 256 thr.
// Warp w owns tokens tok0+w*8 .. +7; lane = k-slice. Direct coalesced LDG of
// x (MLP 8), gw chunk in SMEM (loaded once, single barrier). No x SMEM.
// ---------------------------------------------------------------------------
__global__ __launch_bounds__(256) void gate_part(const float* __restrict__ x,
                                                 const float* __restrict__ gw,
                                                 float* __restrict__ lp)
{
    __shared__ float gs[N_EXP][KCH_G];   // 16 KB

    const int tid  = threadIdx.x;
    const int lane = tid & 31;
    const int warp = tid >> 5;
    const int tok0 = blockIdx.x * 64 + warp * 8;
    const int kc0  = blockIdx.y * KCH_G;

    // cooperative load of gw chunk: 8 rows x 512 floats = 1024 float4
#pragma unroll
    for (int j = 0; j < 4; j++) {
        int li  = tid + j * 256;            // 0..1023
        int row = li >> 7;                  // /128
        int col = (li & 127) * 4;
        *(float4*)&gs[row][col] = *(const float4*)&gw[(size_t)row * DMODEL + kc0 + col];
    }
    __syncthreads();

    float acc[8][8];
#pragma unroll
    for (int i = 0; i < 8; i++)
#pragma unroll
        for (int e = 0; e < 8; e++) acc[i][e] = 0.f;

    const float* xp[8];
#pragma unroll
    for (int i = 0; i < 8; i++)
        xp[i] = &x[(size_t)(tok0 + i) * DMODEL + kc0 + lane];

#pragma unroll 4
    for (int h = 0; h < KCH_G / 32; h++) {
        float xv[8];
#pragma unroll
        for (int i = 0; i < 8; i++) xv[i] = xp[i][h * 32];   // 8 indep LDGs
        float gv[8];
#pragma unroll
        for (int e = 0; e < 8; e++) gv[e] = gs[e][h * 32 + lane];
#pragma unroll
        for (int i = 0; i < 8; i++)
#pragma unroll
            for (int e = 0; e < 8; e++) acc[i][e] += xv[i] * gv[e];
    }

    // butterfly reduce over 32 k-slices
#pragma unroll
    for (int off = 16; off > 0; off >>= 1)
#pragma unroll
        for (int i = 0; i < 8; i++)
#pragma unroll
            for (int e = 0; e < 8; e++)
                acc[i][e] += __shfl_xor_sync(0xffffffffu, acc[i][e], off);

#pragma unroll
    for (int i = 0; i < 8; i++) {
        if (lane == i) {
            int tok = tok0 + i;
            size_t base = ((size_t)blockIdx.y * T_TOK + tok) * N_EXP;
#pragma unroll
            for (int e = 0; e < 8; e++) lp[base + e] = acc[i][e];
        }
    }
}

// ---------------------------------------------------------------------------
// Gate finalize + scatter into per-(slot,expert) lists.
// ---------------------------------------------------------------------------
__global__ __launch_bounds__(256) void gate_fin(const float* __restrict__ lp,
                                                int* __restrict__ cnt,
                                                int* __restrict__ list,
                                                float* __restrict__ wl)
{
    const int tok = blockIdx.x * 256 + threadIdx.x;
    float l[8];
#pragma unroll
    for (int e = 0; e < 8; e++) l[e] = 0.f;
#pragma unroll
    for (int s = 0; s < KSPLIT; s++) {
        size_t base = ((size_t)s * T_TOK + tok) * N_EXP;
#pragma unroll
        for (int e = 0; e < 8; e++) l[e] += lp[base + e];
    }
    float m1 = -1e30f; int e1 = 0;
#pragma unroll
    for (int e = 0; e < 8; e++)
        if (l[e] > m1) { m1 = l[e]; e1 = e; }
    float m2 = -1e30f; int e2 = 0;
#pragma unroll
    for (int e = 0; e < 8; e++)
        if (e != e1 && l[e] > m2) { m2 = l[e]; e2 = e; }
    float w1 = 1.0f / (1.0f + __expf(m2 - m1));

    int p1 = atomicAdd(&cnt[e1], 1);               // slot 0
    list[e1 * T_TOK + p1] = tok;
    wl[e1 * T_TOK + p1] = w1;
    int p2 = atomicAdd(&cnt[8 + e2], 1);           // slot 1
    list[(8 + e2) * T_TOK + p2] = tok;
    wl[(8 + e2) * T_TOK + p2] = 1.0f - w1;
}

// ---------------------------------------------------------------------------
// GEMM1 sparse — measured-best shape + reg cap for 4 CTAs/SM:
// K-split x4, 128 thr (4 warps 2x2, warp tile 64x32), 2-stage cp.async,
// drained tail. A = raw x (HW tf32-truncation).
// ---------------------------------------------------------------------------
#define G1_AT (128 * 36)
#define G1_BT (64 * 36)
#define G1_ST (G1_AT + G1_BT)
#define G1_DYN (2 * G1_ST * 4)

__global__ __launch_bounds__(128, 4) void gemm1_sparse(const float* __restrict__ x,
                                                       const float* __restrict__ Ar,
                                                       const int* __restrict__ cnt,
                                                       const int* __restrict__ list,
                                                       float* __restrict__ Hp)
{
    const int bx  = blockIdx.x;
    const int ks  = bx >> 10;                  // NLIST*MAXTIL = 1024 per split
    const int rem = bx & 1023;
    const int le  = rem >> 6;
    const int mt  = rem & (MAXTIL - 1);
    const int n   = cnt[le];
    if (mt * 128 >= n) return;
    const int e = le & 7;

    __shared__ int toks[128];
    extern __shared__ float sm[];

    const int tid  = threadIdx.x;
    const int lane = tid & 31;
    const int warp = tid >> 5;
    const int wm   = warp >> 1;     // 0..1
    const int wn   = warp & 1;      // 0..1

    toks[tid] = list[le * T_TOK + mt * 128 + tid];
    __syncthreads();

    const uint32_t smbase = (uint32_t)__cvta_generic_to_shared(sm);
    const int lr4 = tid >> 3;          // 0..15
    const int lc4 = (tid & 7) * 4;     // 0..28
    const int kb  = ks * KCHUNK;

    const float* ap[8];
#pragma unroll
    for (int j = 0; j < 8; j++)
        ap[j] = &x[(size_t)toks[lr4 + j * 16] * DMODEL + kb + lc4];
    const float* bp[4];
#pragma unroll
    for (int j = 0; j < 4; j++)
        bp[j] = &Ar[((size_t)e * 64 + lr4 + j * 16) * DMODEL + kb + lc4];

    auto issue = [&](int kt) {
        const int s = kt & 1;
        const int k0 = kt * 32;
        const uint32_t sa = smbase + (uint32_t)(s * G1_ST) * 4u;
        const uint32_t sb = sa + G1_AT * 4u;
#pragma unroll
        for (int j = 0; j < 8; j++)
            cp_async16(sa + ((lr4 + j * 16) * 36 + lc4) * 4u, ap[j] + k0);
#pragma unroll
        for (int j = 0; j < 4; j++)
            cp_async16(sb + ((lr4 + j * 16) * 36 + lc4) * 4u, bp[j] + k0);
    };

    float c[4][4][4] = {};
    issue(0); cp_commit();

    const int r0 = lane >> 2;
    const int cq = lane & 3;
    constexpr int KT = KCHUNK / 32;    // 32

    for (int kt = 0; kt < KT; kt++) {
        if (kt + 1 < KT) { issue(kt + 1); cp_commit(); cp_wait<1>(); }
        else             { cp_wait<0>(); }
        __syncthreads();

        const float* As = sm + (kt & 1) * G1_ST;
        const float* Bs = As + G1_AT;

#pragma unroll
        for (int kk = 0; kk < 4; kk++) {
            const int k8 = kk * 8;
            unsigned a[4][4], b[4][2];
#pragma unroll
            for (int mi = 0; mi < 4; mi++) {
                int rb = wm * 64 + mi * 16 + r0;
                a[mi][0] = __float_as_uint(As[rb * 36 + k8 + cq]);
                a[mi][1] = __float_as_uint(As[(rb + 8) * 36 + k8 + cq]);
                a[mi][2] = __float_as_uint(As[rb * 36 + k8 + cq + 4]);
                a[mi][3] = __float_as_uint(As[(rb + 8) * 36 + k8 + cq + 4]);
            }
#pragma unroll
            for (int ni = 0; ni < 4; ni++) {
                int nb = wn * 32 + ni * 8 + r0;
                b[ni][0] = __float_as_uint(Bs[nb * 36 + k8 + cq]);
                b[ni][1] = __float_as_uint(Bs[nb * 36 + k8 + cq + 4]);
            }
#pragma unroll
            for (int mi = 0; mi < 4; mi++)
#pragma unroll
                for (int ni = 0; ni < 4; ni++)
                    mma_tf32(c[mi][ni], a[mi], b[ni]);
        }
        __syncthreads();
    }

    const size_t base = (size_t)ks * HP_STRIDE + ((size_t)le * T_TOK + mt * 128) * RANK;
#pragma unroll
    for (int mi = 0; mi < 4; mi++) {
#pragma unroll
        for (int ni = 0; ni < 4; ni++) {
            int row = wm * 64 + mi * 16 + r0;
            int col = wn * 32 + ni * 8 + cq * 2;
            *(float2*)&Hp[base + (size_t)row * RANK + col] =
                make_float2(c[mi][ni][0], c[mi][ni][1]);
            *(float2*)&Hp[base + (size_t)(row + 8) * RANK + col] =
                make_float2(c[mi][ni][2], c[mi][ni][3]);
        }
    }
}

// ---------------------------------------------------------------------------
// reduce_H: H[le][i] = round( w_i * sum_ks Hp[ks][le][i] )
// ---------------------------------------------------------------------------
__global__ __launch_bounds__(256) void reduce_H(const float* __restrict__ Hp,
                                                const int* __restrict__ cnt,
                                                const float* __restrict__ wl,
                                                float* __restrict__ H)
{
    const int le = blockIdx.x >> 6;
    const int mt = blockIdx.x & (MAXTIL - 1);
    const int n  = cnt[le];
    if (mt * 128 >= n) return;

    const int tid  = threadIdx.x;
    const int row  = tid >> 1;
    const int half = (tid & 1) * 32;
    const int i    = mt * 128 + row;
    if (i >= n) return;

    const float w = wl[le * T_TOK + i];
    const size_t rb = ((size_t)le * T_TOK + i) * RANK + half;

#pragma unroll
    for (int q = 0; q < 8; q++) {
        float4 s = *(const float4*)&Hp[rb + q * 4];
#pragma unroll
        for (int ks = 1; ks < KS1; ks++) {
            float4 p = *(const float4*)&Hp[(size_t)ks * HP_STRIDE + rb + q * 4];
            s.x += p.x; s.y += p.y; s.z += p.z; s.w += p.w;
        }
        s.x = __uint_as_float(f2tf(s.x * w));
        s.y = __uint_as_float(f2tf(s.y * w));
        s.z = __uint_as_float(f2tf(s.z * w));
        s.w = __uint_as_float(f2tf(s.w * w));
        *(float4*)&H[rb + q * 4] = s;
    }
}

// ---------------------------------------------------------------------------
// GEMM2 sparse: 2 N-tiles per CTA, H loaded ONCE, B double-buffered.
// Tile 128x128 per bn iter, K=64 one-shot. 256 thr, warps 2x4.
// SLOT 0: out[tok] = v ; SLOT 1: out[tok] += v.
// ---------------------------------------------------------------------------
#define G2_HT (128 * 68)                 // floats per tile buffer
#define G2_DYN (3 * G2_HT * 4)           // H + B0 + B1 = 104448 B
#define SO_S  132                        // staging row stride (floats)

template <int SLOT>
__global__ __launch_bounds__(256, 2) void gemm2_sparse(const float* __restrict__ H,
                                                       const float* __restrict__ Br,
                                                       const int* __restrict__ cnt,
                                                       const int* __restrict__ list,
                                                       float* __restrict__ out)
{
    const int e  = blockIdx.y >> 6;
    const int le = SLOT * 8 + e;
    const int mt = blockIdx.y & (MAXTIL - 1);
    const int n  = cnt[le];
    if (mt * 128 >= n) return;
    const int bn0 = blockIdx.x * 256;

    __shared__ int toks[128];
    extern __shared__ float sm[];
    float* Hs = sm;                       // H tile (persistent)
    float* Bb[2] = { sm + G2_HT, sm + 2 * G2_HT };
    float* so = sm + G2_HT;               // staging == B0 region

    const int tid  = threadIdx.x;
    const int lane = tid & 31;
    const int warp = tid >> 5;
    const int wm   = warp >> 2;
    const int wn   = warp & 3;

    if (tid < 128) toks[tid] = list[le * T_TOK + mt * 128 + tid];

    const uint32_t smbase = (uint32_t)__cvta_generic_to_shared(sm);
    const int lr4 = tid >> 4;          // 0..15
    const int lc4 = (tid & 15) * 4;    // 0..60

    // group0 = {H, B(bn0)}, group1 = {B(bn0+128)}
#pragma unroll
    for (int j = 0; j < 8; j++) {
        int row = lr4 + j * 16;
        cp_async16(smbase + (uint32_t)(row * 68 + lc4) * 4u,
                   &H[((size_t)le * T_TOK + mt * 128 + row) * RANK + lc4]);
        cp_async16(smbase + (uint32_t)(G2_HT + row * 68 + lc4) * 4u,
                   &Br[((size_t)e * DMODEL + bn0 + row) * RANK + lc4]);
    }
    cp_commit();
#pragma unroll
    for (int j = 0; j < 8; j++) {
        int row = lr4 + j * 16;
        cp_async16(smbase + (uint32_t)(2 * G2_HT + row * 68 + lc4) * 4u,
                   &Br[((size_t)e * DMODEL + bn0 + 128 + row) * RANK + lc4]);
    }
    cp_commit();

    const int r0 = lane >> 2;
    const int cq = lane & 3;
    const int rr = tid >> 3;            // 0..31 (epilogue row)
    const int kk8 = (tid & 7) * 4;      // 0..28

#pragma unroll 1
    for (int t = 0; t < 2; t++) {
        if (t == 0) cp_wait<1>();       // H + B0 complete
        else        cp_wait<0>();       // B1 complete
        __syncthreads();

        const float* Bs = Bb[t];
        const int bn = bn0 + t * 128;

        float c[4][4][4] = {};
#pragma unroll
        for (int kk = 0; kk < 8; kk++) {
            const int k8 = kk * 8;
            unsigned a[4][4], b[4][2];
#pragma unroll
            for (int mi = 0; mi < 4; mi++) {
                int rb = wm * 64 + mi * 16 + r0;
                a[mi][0] = __float_as_uint(Hs[rb * 68 + k8 + cq]);
                a[mi][1] = __float_as_uint(Hs[(rb + 8) * 68 + k8 + cq]);
                a[mi][2] = __float_as_uint(Hs[rb * 68 + k8 + cq + 4]);
                a[mi][3] = __float_as_uint(Hs[(rb + 8) * 68 + k8 + cq + 4]);
            }
#pragma unroll
            for (int ni = 0; ni < 4; ni++) {
                int nb = wn * 32 + ni * 8 + r0;
                b[ni][0] = __float_as_uint(Bs[nb * 68 + k8 + cq]);
                b[ni][1] = __float_as_uint(Bs[nb * 68 + k8 + cq + 4]);
            }
#pragma unroll
            for (int mi = 0; mi < 4; mi++)
#pragma unroll
                for (int ni = 0; ni < 4; ni++)
                    mma_tf32(c[mi][ni], a[mi], b[ni]);
        }

        // ---- staged coalesced epilogue: 4 groups of 32 rows ----
#pragma unroll
        for (int g = 0; g < 4; g++) {
            __syncthreads();
            if (wm == (g >> 1)) {
                const int m0 = (g & 1) * 2;
#pragma unroll
                for (int mh = 0; mh < 2; mh++) {
                    const int mi = m0 + mh;
                    const int rl = mh * 16 + r0;
#pragma unroll
                    for (int ni = 0; ni < 4; ni++) {
                        const int col = wn * 32 + ni * 8 + cq * 2;
                        *(float2*)&so[rl * SO_S + col] =
                            make_float2(c[mi][ni][0], c[mi][ni][1]);
                        *(float2*)&so[(rl + 8) * SO_S + col] =
                            make_float2(c[mi][ni][2], c[mi][ni][3]);
                    }
                }
            }
            __syncthreads();
            const int gi = mt * 128 + g * 32 + rr;
            if (gi < n) {
                const int tk = toks[g * 32 + rr];
                float* op = &out[(size_t)tk * DMODEL + bn + kk8];
#pragma unroll
                for (int q = 0; q < 4; q++) {
                    float4 v = *(float4*)&so[rr * SO_S + kk8 + q * 32];
                    if (SLOT == 1) {
                        float4 o = *(float4*)&op[q * 32];
                        v.x += o.x; v.y += o.y; v.z += o.z; v.w += o.w;
                    }
                    *(float4*)&op[q * 32] = v;
                }
            }
        }
        __syncthreads();   // staging drained before t=1 reuses it / exits
    }
}

// ---------------------------------------------------------------------------
// launch
// ---------------------------------------------------------------------------
extern "C" void kernel_launch(void* const* d_in, const int* in_sizes, int n_in,
                              void* d_out, int out_size)
{
    const float* x  = (const float*)d_in[0];   // [4,2048,4096]
    const float* gw = (const float*)d_in[1];   // [8,4096]
    const float* lA = (const float*)d_in[2];   // [8,64,4096]
    const float* lB = (const float*)d_in[3];   // [8,4096,64]
    float* out = (float*)d_out;

    float *Hp, *Hc, *lpp, *Ar, *Br, *wlp;
    int *cntp, *listp;
    cudaGetSymbolAddress((void**)&Hp,   g_Hp);
    cudaGetSymbolAddress((void**)&Hc,   g_H);
    cudaGetSymbolAddress((void**)&lpp,  g_lp);
    cudaGetSymbolAddress((void**)&Ar,   g_Ar);
    cudaGetSymbolAddress((void**)&Br,   g_Br);
    cudaGetSymbolAddress((void**)&cntp, g_cnt);
    cudaGetSymbolAddress((void**)&listp,g_list);
    cudaGetSymbolAddress((void**)&wlp,  g_wl);

    cudaFuncSetAttribute((const void*)gemm1_sparse,
                         cudaFuncAttributeMaxDynamicSharedMemorySize, G1_DYN);
    cudaFuncSetAttribute((const void*)gemm2_sparse<0>,
                         cudaFuncAttributeMaxDynamicSharedMemorySize, G2_DYN);
    cudaFuncSetAttribute((const void*)gemm2_sparse<1>,
                         cudaFuncAttributeMaxDynamicSharedMemorySize, G2_DYN);

    // 1) round LoRA weights to tf32 + reset list counters
    round_weights<<<(ER * DMODEL / 4 + 255) / 256, 256>>>(
        (const float4*)lA, (const float4*)lB, (float4*)Ar, (float4*)Br, cntp);
    // 2) gate partials (streaming, K-split x8)
    gate_part<<<dim3(T_TOK / 64, KSPLIT), 256>>>(x, gw, lpp);
    // 3) finalize gate + scatter tokens into (slot, expert) lists
    gate_fin<<<T_TOK / 256, 256>>>(lpp, cntp, listp, wlp);
    // 4) sparse GEMM1 (reg-capped for 4 CTAs/SM)
    gemm1_sparse<<<KS1 * NLIST * MAXTIL, 128, G1_DYN>>>(x, Ar, cntp, listp, Hp);
    // 5) reduce partials + routing weight + tf32-round -> compact H
    reduce_H<<<NLIST * MAXTIL, 256>>>(Hp, cntp, wlp, Hc);
    // 6) sparse GEMM2 pass A (slot 0): out = v   (2 N-tiles per CTA)
    gemm2_sparse<0><<<dim3(DMODEL / 256, N_EXP * MAXTIL), 256, G2_DYN>>>(Hc, Br, cntp, listp, out);
    // 7) sparse GEMM2 pass B (slot 1): out += v
    gemm2_sparse<1><<<dim3(DMODEL / 256, N_EXP * MAXTIL), 256, G2_DYN>>>(Hc, Br, cntp, listp, out);
}

// round 13
// speedup vs baseline: 1.1259x; 1.0127x over previous
#include <cuda_runtime.h>
#include <cstdint>

// Fixed shapes for TopKGOATLayer_74156905333517
#define T_TOK   8192
#define DMODEL  4096
#define N_EXP   8
#define RANK    64
#define ER      512
#define KSPLIT  8
#define KCH_G   (DMODEL / KSPLIT)   // 512, gate k-chunk
#define MAXTIL  64          // worst-case M-tiles per list (8192/128)
#define NLIST   16          // (slot, expert)
#define KS1     4           // K-split factor for gemm1
#define KCHUNK  (DMODEL / KS1)
#define HP_STRIDE ((size_t)NLIST * T_TOK * RANK)

// Scratch (__device__ globals)
__device__ __align__(16) float g_Ar[ER * DMODEL];           // tf32-rounded lora_A
__device__ __align__(16) float g_Br[N_EXP * DMODEL * RANK]; // tf32-rounded lora_B
__device__ __align__(16) float g_Hp[KS1 * NLIST * T_TOK * RANK]; // gemm1 partials
__device__ __align__(16) float g_H[NLIST * T_TOK * RANK];   // compact Hw per (slot,e)
__device__ float g_lp[KSPLIT * T_TOK * N_EXP];
__device__ int   g_cnt[NLIST];
__device__ int   g_list[NLIST * T_TOK];
__device__ float g_wl[NLIST * T_TOK];

// ---------------------------------------------------------------------------
// helpers
// ---------------------------------------------------------------------------
__device__ __forceinline__ unsigned f2tf(float f) {
    unsigned r;
    asm("cvt.rna.tf32.f32 %0, %1;" : "=r"(r) : "f"(f));
    return r;
}

__device__ __forceinline__ void mma_tf32(float c[4], const unsigned a[4], const unsigned b[2]) {
    asm volatile(
        "mma.sync.aligned.m16n8k8.row.col.f32.tf32.tf32.f32 "
        "{%0,%1,%2,%3}, {%4,%5,%6,%7}, {%8,%9}, {%0,%1,%2,%3};\n"
        : "+f"(c[0]), "+f"(c[1]), "+f"(c[2]), "+f"(c[3])
        : "r"(a[0]), "r"(a[1]), "r"(a[2]), "r"(a[3]), "r"(b[0]), "r"(b[1]));
}

__device__ __forceinline__ void cp_async16(uint32_t saddr, const void* gaddr) {
    asm volatile("cp.async.cg.shared.global [%0], [%1], 16;\n" :: "r"(saddr), "l"(gaddr));
}
__device__ __forceinline__ void cp_commit() { asm volatile("cp.async.commit_group;\n"); }
template <int N> __device__ __forceinline__ void cp_wait() {
    asm volatile("cp.async.wait_group %0;\n" :: "n"(N));
}

// ---------------------------------------------------------------------------
// tf32 pre-rounding of LoRA weights + counter reset
// ---------------------------------------------------------------------------
__global__ __launch_bounds__(256) void round_weights(const float4* __restrict__ lA,
                                                     const float4* __restrict__ lB,
                                                     float4* __restrict__ Ar,
                                                     float4* __restrict__ Br,
                                                     int* __restrict__ cnt)
{
    const int n4 = ER * DMODEL / 4;
    int i = blockIdx.x * 256 + threadIdx.x;
    if (i < n4) {
        float4 v = lA[i];
        v.x = __uint_as_float(f2tf(v.x));
        v.y = __uint_as_float(f2tf(v.y));
        v.z = __uint_as_float(f2tf(v.z));
        v.w = __uint_as_float(f2tf(v.w));
        Ar[i] = v;
        float4 u = lB[i];
        u.x = __uint_as_float(f2tf(u.x));
        u.y = __uint_as_float(f2tf(u.y));
        u.z = __uint_as_float(f2tf(u.z));
        u.w = __uint_as_float(f2tf(u.w));
        Br[i] = u;
    }
    if (blockIdx.x == 0 && threadIdx.x < NLIST) cnt[threadIdx.x] = 0;
}

// ---------------------------------------------------------------------------
// Gate partials — streaming. grid = (T/64, KSPLIT=8), 256 thr.
// ---------------------------------------------------------------------------
__global__ __launch_bounds__(256) void gate_part(const float* __restrict__ x,
                                                 const float* __restrict__ gw,
                                                 float* __restrict__ lp)
{
    __shared__ float gs[N_EXP][KCH_G];   // 16 KB

    const int tid  = threadIdx.x;
    const int lane = tid & 31;
    const int warp = tid >> 5;
    const int tok0 = blockIdx.x * 64 + warp * 8;
    const int kc0  = blockIdx.y * KCH_G;

#pragma unroll
    for (int j = 0; j < 4; j++) {
        int li  = tid + j * 256;
        int row = li >> 7;
        int col = (li & 127) * 4;
        *(float4*)&gs[row][col] = *(const float4*)&gw[(size_t)row * DMODEL + kc0 + col];
    }
    __syncthreads();

    float acc[8][8];
#pragma unroll
    for (int i = 0; i < 8; i++)
#pragma unroll
        for (int e = 0; e < 8; e++) acc[i][e] = 0.f;

    const float* xp[8];
#pragma unroll
    for (int i = 0; i < 8; i++)
        xp[i] = &x[(size_t)(tok0 + i) * DMODEL + kc0 + lane];

#pragma unroll 4
    for (int h = 0; h < KCH_G / 32; h++) {
        float xv[8];
#pragma unroll
        for (int i = 0; i < 8; i++) xv[i] = xp[i][h * 32];
        float gv[8];
#pragma unroll
        for (int e = 0; e < 8; e++) gv[e] = gs[e][h * 32 + lane];
#pragma unroll
        for (int i = 0; i < 8; i++)
#pragma unroll
            for (int e = 0; e < 8; e++) acc[i][e] += xv[i] * gv[e];
    }

#pragma unroll
    for (int off = 16; off > 0; off >>= 1)
#pragma unroll
        for (int i = 0; i < 8; i++)
#pragma unroll
            for (int e = 0; e < 8; e++)
                acc[i][e] += __shfl_xor_sync(0xffffffffu, acc[i][e], off);

#pragma unroll
    for (int i = 0; i < 8; i++) {
        if (lane == i) {
            int tok = tok0 + i;
            size_t base = ((size_t)blockIdx.y * T_TOK + tok) * N_EXP;
#pragma unroll
            for (int e = 0; e < 8; e++) lp[base + e] = acc[i][e];
        }
    }
}

// ---------------------------------------------------------------------------
// Gate finalize + scatter into per-(slot,expert) lists.
// ---------------------------------------------------------------------------
__global__ __launch_bounds__(256) void gate_fin(const float* __restrict__ lp,
                                                int* __restrict__ cnt,
                                                int* __restrict__ list,
                                                float* __restrict__ wl)
{
    const int tok = blockIdx.x * 256 + threadIdx.x;
    float l[8];
#pragma unroll
    for (int e = 0; e < 8; e++) l[e] = 0.f;
#pragma unroll
    for (int s = 0; s < KSPLIT; s++) {
        size_t base = ((size_t)s * T_TOK + tok) * N_EXP;
#pragma unroll
        for (int e = 0; e < 8; e++) l[e] += lp[base + e];
    }
    float m1 = -1e30f; int e1 = 0;
#pragma unroll
    for (int e = 0; e < 8; e++)
        if (l[e] > m1) { m1 = l[e]; e1 = e; }
    float m2 = -1e30f; int e2 = 0;
#pragma unroll
    for (int e = 0; e < 8; e++)
        if (e != e1 && l[e] > m2) { m2 = l[e]; e2 = e; }
    float w1 = 1.0f / (1.0f + __expf(m2 - m1));

    int p1 = atomicAdd(&cnt[e1], 1);               // slot 0
    list[e1 * T_TOK + p1] = tok;
    wl[e1 * T_TOK + p1] = w1;
    int p2 = atomicAdd(&cnt[8 + e2], 1);           // slot 1
    list[(8 + e2) * T_TOK + p2] = tok;
    wl[(8 + e2) * T_TOK + p2] = 1.0f - w1;
}

// ---------------------------------------------------------------------------
// GEMM1 sparse — frozen at R12 state (74.6us plateau).
// ---------------------------------------------------------------------------
#define G1_AT (128 * 36)
#define G1_BT (64 * 36)
#define G1_ST (G1_AT + G1_BT)
#define G1_DYN (2 * G1_ST * 4)

__global__ __launch_bounds__(128, 4) void gemm1_sparse(const float* __restrict__ x,
                                                       const float* __restrict__ Ar,
                                                       const int* __restrict__ cnt,
                                                       const int* __restrict__ list,
                                                       float* __restrict__ Hp)
{
    const int bx  = blockIdx.x;
    const int ks  = bx >> 10;
    const int rem = bx & 1023;
    const int le  = rem >> 6;
    const int mt  = rem & (MAXTIL - 1);
    const int n   = cnt[le];
    if (mt * 128 >= n) return;
    const int e = le & 7;

    __shared__ int toks[128];
    extern __shared__ float sm[];

    const int tid  = threadIdx.x;
    const int lane = tid & 31;
    const int warp = tid >> 5;
    const int wm   = warp >> 1;
    const int wn   = warp & 1;

    toks[tid] = list[le * T_TOK + mt * 128 + tid];
    __syncthreads();

    const uint32_t smbase = (uint32_t)__cvta_generic_to_shared(sm);
    const int lr4 = tid >> 3;
    const int lc4 = (tid & 7) * 4;
    const int kb  = ks * KCHUNK;

    const float* ap[8];
#pragma unroll
    for (int j = 0; j < 8; j++)
        ap[j] = &x[(size_t)toks[lr4 + j * 16] * DMODEL + kb + lc4];
    const float* bp[4];
#pragma unroll
    for (int j = 0; j < 4; j++)
        bp[j] = &Ar[((size_t)e * 64 + lr4 + j * 16) * DMODEL + kb + lc4];

    auto issue = [&](int kt) {
        const int s = kt & 1;
        const int k0 = kt * 32;
        const uint32_t sa = smbase + (uint32_t)(s * G1_ST) * 4u;
        const uint32_t sb = sa + G1_AT * 4u;
#pragma unroll
        for (int j = 0; j < 8; j++)
            cp_async16(sa + ((lr4 + j * 16) * 36 + lc4) * 4u, ap[j] + k0);
#pragma unroll
        for (int j = 0; j < 4; j++)
            cp_async16(sb + ((lr4 + j * 16) * 36 + lc4) * 4u, bp[j] + k0);
    };

    float c[4][4][4] = {};
    issue(0); cp_commit();

    const int r0 = lane >> 2;
    const int cq = lane & 3;
    constexpr int KT = KCHUNK / 32;

    for (int kt = 0; kt < KT; kt++) {
        if (kt + 1 < KT) { issue(kt + 1); cp_commit(); cp_wait<1>(); }
        else             { cp_wait<0>(); }
        __syncthreads();

        const float* As = sm + (kt & 1) * G1_ST;
        const float* Bs = As + G1_AT;

#pragma unroll
        for (int kk = 0; kk < 4; kk++) {
            const int k8 = kk * 8;
            unsigned a[4][4], b[4][2];
#pragma unroll
            for (int mi = 0; mi < 4; mi++) {
                int rb = wm * 64 + mi * 16 + r0;
                a[mi][0] = __float_as_uint(As[rb * 36 + k8 + cq]);
                a[mi][1] = __float_as_uint(As[(rb + 8) * 36 + k8 + cq]);
                a[mi][2] = __float_as_uint(As[rb * 36 + k8 + cq + 4]);
                a[mi][3] = __float_as_uint(As[(rb + 8) * 36 + k8 + cq + 4]);
            }
#pragma unroll
            for (int ni = 0; ni < 4; ni++) {
                int nb = wn * 32 + ni * 8 + r0;
                b[ni][0] = __float_as_uint(Bs[nb * 36 + k8 + cq]);
                b[ni][1] = __float_as_uint(Bs[nb * 36 + k8 + cq + 4]);
            }
#pragma unroll
            for (int mi = 0; mi < 4; mi++)
#pragma unroll
                for (int ni = 0; ni < 4; ni++)
                    mma_tf32(c[mi][ni], a[mi], b[ni]);
        }
        __syncthreads();
    }

    const size_t base = (size_t)ks * HP_STRIDE + ((size_t)le * T_TOK + mt * 128) * RANK;
#pragma unroll
    for (int mi = 0; mi < 4; mi++) {
#pragma unroll
        for (int ni = 0; ni < 4; ni++) {
            int row = wm * 64 + mi * 16 + r0;
            int col = wn * 32 + ni * 8 + cq * 2;
            *(float2*)&Hp[base + (size_t)row * RANK + col] =
                make_float2(c[mi][ni][0], c[mi][ni][1]);
            *(float2*)&Hp[base + (size_t)(row + 8) * RANK + col] =
                make_float2(c[mi][ni][2], c[mi][ni][3]);
        }
    }
}

// ---------------------------------------------------------------------------
// reduce_H: H[le][i] = round( w_i * sum_ks Hp[ks][le][i] )
// ---------------------------------------------------------------------------
__global__ __launch_bounds__(256) void reduce_H(const float* __restrict__ Hp,
                                                const int* __restrict__ cnt,
                                                const float* __restrict__ wl,
                                                float* __restrict__ H)
{
    const int le = blockIdx.x >> 6;
    const int mt = blockIdx.x & (MAXTIL - 1);
    const int n  = cnt[le];
    if (mt * 128 >= n) return;

    const int tid  = threadIdx.x;
    const int row  = tid >> 1;
    const int half = (tid & 1) * 32;
    const int i    = mt * 128 + row;
    if (i >= n) return;

    const float w = wl[le * T_TOK + i];
    const size_t rb = ((size_t)le * T_TOK + i) * RANK + half;

#pragma unroll
    for (int q = 0; q < 8; q++) {
        float4 s = *(const float4*)&Hp[rb + q * 4];
#pragma unroll
        for (int ks = 1; ks < KS1; ks++) {
            float4 p = *(const float4*)&Hp[(size_t)ks * HP_STRIDE + rb + q * 4];
            s.x += p.x; s.y += p.y; s.z += p.z; s.w += p.w;
        }
        s.x = __uint_as_float(f2tf(s.x * w));
        s.y = __uint_as_float(f2tf(s.y * w));
        s.z = __uint_as_float(f2tf(s.z * w));
        s.w = __uint_as_float(f2tf(s.w * w));
        *(float4*)&H[rb + q * 4] = s;
    }
}

// ---------------------------------------------------------------------------
// GEMM2 sparse: 4 N-tiles per CTA, H loaded ONCE, B ring double-buffered and
// overlapped with compute+epilogue. Staging reuses the B buffer just computed
// from. SLOT 0: out[tok] = v ; SLOT 1: out[tok] += v.
// Group schedule: G0={H,B0}, G1={B1}, then B(t+2) issued after epilogue t.
// At tile t the outstanding groups are {B(t), B(t+1)} -> wait<1> (last: wait<0>).
// ---------------------------------------------------------------------------
#define NT2   4                          // N-tiles per CTA
#define G2_HT (128 * 68)                 // floats per tile buffer
#define G2_DYN (3 * G2_HT * 4)           // H + Bb0 + Bb1 = 104448 B
#define SO_S  132                        // staging row stride (floats)

template <int SLOT>
__global__ __launch_bounds__(256, 2) void gemm2_sparse(const float* __restrict__ H,
                                                       const float* __restrict__ Br,
                                                       const int* __restrict__ cnt,
                                                       const int* __restrict__ list,
                                                       float* __restrict__ out)
{
    const int e  = blockIdx.y >> 6;
    const int le = SLOT * 8 + e;
    const int mt = blockIdx.y & (MAXTIL - 1);
    const int n  = cnt[le];
    if (mt * 128 >= n) return;
    const int bn0 = blockIdx.x * (NT2 * 128);

    __shared__ int toks[128];
    extern __shared__ float sm[];
    float* Hs = sm;                       // H tile (persistent)

    const int tid  = threadIdx.x;
    const int lane = tid & 31;
    const int warp = tid >> 5;
    const int wm   = warp >> 2;
    const int wn   = warp & 3;

    if (tid < 128) toks[tid] = list[le * T_TOK + mt * 128 + tid];

    const uint32_t smbase = (uint32_t)__cvta_generic_to_shared(sm);
    const int lr4 = tid >> 4;          // 0..15
    const int lc4 = (tid & 15) * 4;    // 0..60

    auto issueB = [&](int t) {
        const uint32_t boff = (uint32_t)((1 + (t & 1)) * G2_HT) * 4u;
#pragma unroll
        for (int j = 0; j < 8; j++) {
            int row = lr4 + j * 16;
            cp_async16(smbase + boff + (uint32_t)(row * 68 + lc4) * 4u,
                       &Br[((size_t)e * DMODEL + bn0 + t * 128 + row) * RANK + lc4]);
        }
    };

    // G0 = {H, B0}
#pragma unroll
    for (int j = 0; j < 8; j++) {
        int row = lr4 + j * 16;
        cp_async16(smbase + (uint32_t)(row * 68 + lc4) * 4u,
                   &H[((size_t)le * T_TOK + mt * 128 + row) * RANK + lc4]);
    }
    issueB(0);
    cp_commit();
    // G1 = {B1}
    issueB(1);
    cp_commit();

    const int r0 = lane >> 2;
    const int cq = lane & 3;
    const int rr = tid >> 3;            // 0..31 (epilogue row)
    const int kk8 = (tid & 7) * 4;      // 0..28

#pragma unroll 1
    for (int t = 0; t < NT2; t++) {
        if (t < NT2 - 1) cp_wait<1>();  // B(t) (and H for t=0) complete
        else             cp_wait<0>();
        __syncthreads();

        const float* Bs = sm + (1 + (t & 1)) * G2_HT;
        float* so = sm + (1 + (t & 1)) * G2_HT;   // staging = this tile's B buf
        const int bn = bn0 + t * 128;

        float c[4][4][4] = {};
#pragma unroll
        for (int kk = 0; kk < 8; kk++) {
            const int k8 = kk * 8;
            unsigned a[4][4], b[4][2];
#pragma unroll
            for (int mi = 0; mi < 4; mi++) {
                int rb = wm * 64 + mi * 16 + r0;
                a[mi][0] = __float_as_uint(Hs[rb * 68 + k8 + cq]);
                a[mi][1] = __float_as_uint(Hs[(rb + 8) * 68 + k8 + cq]);
                a[mi][2] = __float_as_uint(Hs[rb * 68 + k8 + cq + 4]);
                a[mi][3] = __float_as_uint(Hs[(rb + 8) * 68 + k8 + cq + 4]);
            }
#pragma unroll
            for (int ni = 0; ni < 4; ni++) {
                int nb = wn * 32 + ni * 8 + r0;
                b[ni][0] = __float_as_uint(Bs[nb * 68 + k8 + cq]);
                b[ni][1] = __float_as_uint(Bs[nb * 68 + k8 + cq + 4]);
            }
#pragma unroll
            for (int mi = 0; mi < 4; mi++)
#pragma unroll
                for (int ni = 0; ni < 4; ni++)
                    mma_tf32(c[mi][ni], a[mi], b[ni]);
        }

        // ---- staged coalesced epilogue: 4 groups of 32 rows ----
        // Staging overwrites this tile's B buffer (compute finished); the
        // other B buffer holds the in-flight B(t+1).
#pragma unroll
        for (int g = 0; g < 4; g++) {
            __syncthreads();
            if (wm == (g >> 1)) {
                const int m0 = (g & 1) * 2;
#pragma unroll
                for (int mh = 0; mh < 2; mh++) {
                    const int mi = m0 + mh;
                    const int rl = mh * 16 + r0;
#pragma unroll
                    for (int ni = 0; ni < 4; ni++) {
                        const int col = wn * 32 + ni * 8 + cq * 2;
                        *(float2*)&so[rl * SO_S + col] =
                            make_float2(c[mi][ni][0], c[mi][ni][1]);
                        *(float2*)&so[(rl + 8) * SO_S + col] =
                            make_float2(c[mi][ni][2], c[mi][ni][3]);
                    }
                }
            }
            __syncthreads();
            const int gi = mt * 128 + g * 32 + rr;
            if (gi < n) {
                const int tk = toks[g * 32 + rr];
                float* op = &out[(size_t)tk * DMODEL + bn + kk8];
#pragma unroll
                for (int q = 0; q < 4; q++) {
                    float4 v = *(float4*)&so[rr * SO_S + kk8 + q * 32];
                    if (SLOT == 1) {
                        float4 o = *(float4*)&op[q * 32];
                        v.x += o.x; v.y += o.y; v.z += o.z; v.w += o.w;
                    }
                    *(float4*)&op[q * 32] = v;
                }
            }
        }
        __syncthreads();   // epilogue drained before buffer (t&1) is refilled

        if (t + 2 < NT2) { issueB(t + 2); cp_commit(); }
    }
}

// ---------------------------------------------------------------------------
// launch
// ---------------------------------------------------------------------------
extern "C" void kernel_launch(void* const* d_in, const int* in_sizes, int n_in,
                              void* d_out, int out_size)
{
    const float* x  = (const float*)d_in[0];   // [4,2048,4096]
    const float* gw = (const float*)d_in[1];   // [8,4096]
    const float* lA = (const float*)d_in[2];   // [8,64,4096]
    const float* lB = (const float*)d_in[3];   // [8,4096,64]
    float* out = (float*)d_out;

    float *Hp, *Hc, *lpp, *Ar, *Br, *wlp;
    int *cntp, *listp;
    cudaGetSymbolAddress((void**)&Hp,   g_Hp);
    cudaGetSymbolAddress((void**)&Hc,   g_H);
    cudaGetSymbolAddress((void**)&lpp,  g_lp);
    cudaGetSymbolAddress((void**)&Ar,   g_Ar);
    cudaGetSymbolAddress((void**)&Br,   g_Br);
    cudaGetSymbolAddress((void**)&cntp, g_cnt);
    cudaGetSymbolAddress((void**)&listp,g_list);
    cudaGetSymbolAddress((void**)&wlp,  g_wl);

    cudaFuncSetAttribute((const void*)gemm1_sparse,
                         cudaFuncAttributeMaxDynamicSharedMemorySize, G1_DYN);
    cudaFuncSetAttribute((const void*)gemm2_sparse<0>,
                         cudaFuncAttributeMaxDynamicSharedMemorySize, G2_DYN);
    cudaFuncSetAttribute((const void*)gemm2_sparse<1>,
                         cudaFuncAttributeMaxDynamicSharedMemorySize, G2_DYN);

    // 1) round LoRA weights to tf32 + reset list counters
    round_weights<<<(ER * DMODEL / 4 + 255) / 256, 256>>>(
        (const float4*)lA, (const float4*)lB, (float4*)Ar, (float4*)Br, cntp);
    // 2) gate partials (streaming, K-split x8)
    gate_part<<<dim3(T_TOK / 64, KSPLIT), 256>>>(x, gw, lpp);
    // 3) finalize gate + scatter tokens into (slot, expert) lists
    gate_fin<<<T_TOK / 256, 256>>>(lpp, cntp, listp, wlp);
    // 4) sparse GEMM1 (frozen)
    gemm1_sparse<<<KS1 * NLIST * MAXTIL, 128, G1_DYN>>>(x, Ar, cntp, listp, Hp);
    // 5) reduce partials + routing weight + tf32-round -> compact H
    reduce_H<<<NLIST * MAXTIL, 256>>>(Hp, cntp, wlp, Hc);
    // 6) sparse GEMM2 pass A (slot 0): out = v   (4 N-tiles per CTA)
    gemm2_sparse<0><<<dim3(DMODEL / (NT2 * 128), N_EXP * MAXTIL), 256, G2_DYN>>>(Hc, Br, cntp, listp, out);
    // 7) sparse GEMM2 pass B (slot 1): out += v
    gemm2_sparse<1><<<dim3(DMODEL / (NT2 * 128), N_EXP * MAXTIL), 256, G2_DYN>>>(Hc, Br, cntp, listp, out);
}